// round 5
// baseline (speedup 1.0000x reference)
#include <cuda_runtime.h>
#include <cstdint>

// Problem constants
#define N_ 32
#define D_ 128
#define S_ 128
#define M_ 64
#define MM_ (M_*M_)

// ---------------- scratch (__device__ globals; no allocations allowed) ----------------
__device__ float g_mcdg[N_*D_*M_*2]; // interleaved (mc, dg) pairs: [(n*D+d)*64 + v] -> float2
__device__ float g_md[N_*D_];        // mean of diag
__device__ float g_ma[N_*D_];        // mean of all
__device__ float g_c2[D_*S_];        // coeffs[:,:,1], tf32-rounded, layout [d][s]
__device__ float g_c13[D_*S_*2];     // (0.5*c1, 0.5*c3) interleaved, layout [d][s][2]
__device__ float g_c45[D_*S_*2];     // (c4, c5) interleaved
__device__ float g_P[N_*S_*M_];      // P[n,s,v]
__device__ float g_Q[N_*S_];         // Q[n,s] (includes bias)

__device__ __forceinline__ float tf32r(float x) {
    uint32_t r;
    asm("cvt.rna.tf32.f32 %0, %1;" : "=r"(r) : "f"(x));
    return __uint_as_float(r);
}

__device__ __forceinline__ void cp16(void* s, const void* g) {
    uint32_t sa = (uint32_t)__cvta_generic_to_shared(s);
    asm volatile("cp.async.cg.shared.global [%0], [%1], 16;\n" :: "r"(sa), "l"(g));
}
#define CP_COMMIT() asm volatile("cp.async.commit_group;\n" ::: "memory")
#define CP_WAIT(Nn) asm volatile("cp.async.wait_group %0;\n" :: "n"(Nn) : "memory")

// ---------------- kernel 0: split coeffs ----------------
__global__ void prep_coeffs_kernel(const float* __restrict__ coeffs) {
    int idx = blockIdx.x * blockDim.x + threadIdx.x;   // idx = d*S + s
    if (idx < D_*S_) {
        const float* c = coeffs + idx * 5;
        g_c2[idx]        = tf32r(c[1]);      // pre-rounded for tensor-core GEMM
        g_c13[idx*2]     = 0.5f * c[0];
        g_c13[idx*2 + 1] = 0.5f * c[2];
        g_c45[idx*2]     = c[3];
        g_c45[idx*2 + 1] = c[4];
    }
}

// ---------------- kernel 1: per-(n,d) stats ----------------
__global__ __launch_bounds__(128) void stats_kernel(const float* __restrict__ x) {
    int nd = blockIdx.x;
    const float* p = x + (size_t)nd * MM_;
    int t = threadIdx.x;
    int q = t & 15;          // float4 column group
    int r = t >> 4;          // 0..7

    float4 acc = make_float4(0.f, 0.f, 0.f, 0.f);
    #pragma unroll
    for (int i = 0; i < 8; i++) {
        float4 v = *(const float4*)&p[(i*8 + r)*M_ + q*4];
        acc.x += v.x; acc.y += v.y; acc.z += v.z; acc.w += v.w;
    }

    __shared__ float4 part[128];
    __shared__ float  red[16], red2[16];
    __shared__ float  diags[64];
    part[t] = acc;
    if (t < M_) diags[t] = p[t*M_ + t];
    __syncthreads();

    if (t < 16) {
        float4 cs = part[t];
        #pragma unroll
        for (int rr = 1; rr < 8; rr++) {
            float4 v = part[rr*16 + t];
            cs.x += v.x; cs.y += v.y; cs.z += v.z; cs.w += v.w;
        }
        float mc[4] = { cs.x * (1.0f/M_), cs.y * (1.0f/M_),
                        cs.z * (1.0f/M_), cs.w * (1.0f/M_) };
        float2* out2 = ((float2*)g_mcdg) + nd*M_ + t*4;
        #pragma unroll
        for (int c = 0; c < 4; c++) {
            float2 md2; md2.x = mc[c]; md2.y = diags[t*4 + c];
            out2[c] = md2;
        }
        red[t]  = cs.x + cs.y + cs.z + cs.w;
        red2[t] = diags[t] + diags[t+16] + diags[t+32] + diags[t+48];
    }
    __syncthreads();
    if (t == 0) {
        float sa = 0.f, sd = 0.f;
        #pragma unroll
        for (int k = 0; k < 16; k++) { sa += red[k]; sd += red2[k]; }
        g_ma[nd] = sa * (1.0f/MM_);
        g_md[nd] = sd * (1.0f/M_);
    }
}

// ---------------- kernel 2: P[n,s,v] and Q[n,s] ----------------
// grid (S/8, N); 128 threads: v = tid&63, half = tid>>6 splits the d-loop.
__global__ __launch_bounds__(128) void pq_kernel(const float* __restrict__ bias) {
    int n   = blockIdx.y;
    int s0  = blockIdx.x * 8;
    int tid = threadIdx.x;
    int v   = tid & 63;
    int h   = tid >> 6;

    __shared__ float2 c13s[D_][8];
    __shared__ float  psum[64][8];
    const float2* c13g = (const float2*)g_c13;
    for (int idx = tid; idx < D_ * 8; idx += 128) {
        int d = idx >> 3, t = idx & 7;
        c13s[d][t] = c13g[d*S_ + s0 + t];
    }
    __syncthreads();

    const float2* mcdg = (const float2*)g_mcdg;
    float acc[8] = {0.f,0.f,0.f,0.f,0.f,0.f,0.f,0.f};
    int base = (n*D_ + h*64)*M_ + v;
    #pragma unroll 4
    for (int dd = 0; dd < 64; dd++) {
        float2 m = mcdg[base + dd*M_];
        int d = h*64 + dd;
        #pragma unroll
        for (int t = 0; t < 8; t++) {
            float2 c = c13s[d][t];
            acc[t] += c.x * m.x + c.y * m.y;
        }
    }
    if (h == 1) {
        #pragma unroll
        for (int t = 0; t < 8; t++) psum[v][t] = acc[t];
    }
    __syncthreads();
    if (h == 0) {
        #pragma unroll
        for (int t = 0; t < 8; t++)
            g_P[(n*S_ + s0 + t)*M_ + v] = acc[t] + psum[v][t];
    }

    if (tid < 8) {
        int s = s0 + tid;
        const float2* c45g = (const float2*)g_c45;
        float q = 0.f;
        #pragma unroll 4
        for (int d = 0; d < D_; d++) {
            float2 c = c45g[d*S_ + s];
            q += c.x * g_md[n*D_ + d] + c.y * g_ma[n*D_ + d];
        }
        g_Q[n*S_ + s] = q + bias[s];
    }
}

// ---------------- kernel 3: TF32 tensor-core GEMM, 5-stage cp.async pipeline ----------
// Per n: C[128 s, 4096 ij] = A[s,d] * B[d,ij]. CTA tile 128s x 128ij, BK=8, 16 chunks.
// 8 warps, warp (wr,wc): 32s x 64ij = 2 m-tiles x 8 n-tiles of m16n8k8.
#define BKP    8
#define STAGES 5
#define LDAS   136   // 128 + 8 skew -> conflict-free fragment gathers
#define NCHUNK (D_ / BKP)   // 16

__global__ __launch_bounds__(256, 2) void gemm_tf32_kernel(const float* __restrict__ x,
                                                           float* __restrict__ out) {
    __shared__ float As[STAGES][BKP][LDAS];   // A[s,k] chunk: As[st][k][s]
    __shared__ float Bs[STAGES][BKP][LDAS];   // B[k,ij] chunk

    int n   = blockIdx.y;
    int bx  = blockIdx.x;          // ij chunk (128 wide)
    int tid = threadIdx.x;
    int w    = tid >> 5, lane = tid & 31;
    int g    = lane >> 2, tig = lane & 3;
    int wr   = w & 3;              // s0  = wr*32
    int wc   = w >> 2;             // ij0 = wc*64

    const float* xb = x + (size_t)(n * D_) * MM_ + bx * 128;

    // loader: 256 float4 per (A or B) chunk -> 1 each per thread
    int lr = tid >> 5;             // row 0..7 within chunk
    int lc = (tid & 31) * 4;       // col 0..124

    const float* agp = &g_c2[lr * S_ + lc];
    const float* bgp = &xb[(size_t)lr * MM_ + lc];

    // prologue: prefetch stages 0..3 (chunks 0..3)
    #pragma unroll
    for (int st = 0; st < STAGES - 1; st++) {
        cp16(&As[st][lr][lc], agp + st * BKP * S_);
        cp16(&Bs[st][lr][lc], bgp + (size_t)st * BKP * MM_);
        CP_COMMIT();
    }

    float acc[2][8][4];
    #pragma unroll
    for (int mt = 0; mt < 2; mt++)
        #pragma unroll
        for (int nt = 0; nt < 8; nt++)
            #pragma unroll
            for (int v = 0; v < 4; v++) acc[mt][nt][v] = 0.f;

    int sc = 0;                    // consume stage
    int sp = STAGES - 1;           // produce stage
    #pragma unroll 1
    for (int kt = 0; kt < NCHUNK; kt++) {
        CP_WAIT(3);                // chunk kt resident
        __syncthreads();           // all warps done with stage sp (consumed last iter)

        if (kt + STAGES - 1 < NCHUNK) {
            int d0 = (kt + STAGES - 1) * BKP;
            cp16(&As[sp][lr][lc], agp + d0 * S_);
            cp16(&Bs[sp][lr][lc], bgp + (size_t)d0 * MM_);
        }
        CP_COMMIT();               // empty groups at the tail keep the count uniform

        // compute on stage sc (one k8 block)
        {
            uint32_t a[2][4], b[8][2];
            #pragma unroll
            for (int mt = 0; mt < 2; mt++) {
                int sb = wr * 32 + mt * 16;
                a[mt][0] = __float_as_uint(As[sc][tig    ][sb + g    ]);
                a[mt][1] = __float_as_uint(As[sc][tig    ][sb + g + 8]);
                a[mt][2] = __float_as_uint(As[sc][tig + 4][sb + g    ]);
                a[mt][3] = __float_as_uint(As[sc][tig + 4][sb + g + 8]);
            }
            #pragma unroll
            for (int nt = 0; nt < 8; nt++) {
                int cb = wc * 64 + nt * 8 + g;
                b[nt][0] = __float_as_uint(Bs[sc][tig    ][cb]);
                b[nt][1] = __float_as_uint(Bs[sc][tig + 4][cb]);
            }
            #pragma unroll
            for (int mt = 0; mt < 2; mt++)
                #pragma unroll
                for (int nt = 0; nt < 8; nt++) {
                    asm volatile(
                        "mma.sync.aligned.m16n8k8.row.col.f32.tf32.tf32.f32 "
                        "{%0,%1,%2,%3}, {%4,%5,%6,%7}, {%8,%9}, {%0,%1,%2,%3};"
                        : "+f"(acc[mt][nt][0]), "+f"(acc[mt][nt][1]),
                          "+f"(acc[mt][nt][2]), "+f"(acc[mt][nt][3])
                        : "r"(a[mt][0]), "r"(a[mt][1]), "r"(a[mt][2]), "r"(a[mt][3]),
                          "r"(b[nt][0]), "r"(b[nt][1]));
                }
        }

        sc = (sc == STAGES-1) ? 0 : sc + 1;
        sp = (sp == STAGES-1) ? 0 : sp + 1;
    }

    // epilogue: out = acc + P[n,s,i] + P[n,s,j] + Q[n,s];  i = bx*2 + wc
    int i_row = bx * 2 + wc;
    #pragma unroll
    for (int mt = 0; mt < 2; mt++) {
        #pragma unroll
        for (int half = 0; half < 2; half++) {
            int s = wr * 32 + mt * 16 + g + half * 8;
            const float* Pn = &g_P[(n*S_ + s) * M_];
            float bias_si = Pn[i_row] + g_Q[n*S_ + s];
            size_t obase = (size_t)(n*S_ + s) * MM_ + (size_t)bx * 128 + wc * 64;
            #pragma unroll
            for (int nt = 0; nt < 8; nt++) {
                int j = nt * 8 + 2 * tig;
                float2 r;
                r.x = acc[mt][nt][half*2 + 0] + bias_si + Pn[j];
                r.y = acc[mt][nt][half*2 + 1] + bias_si + Pn[j + 1];
                *(float2*)&out[obase + j] = r;
            }
        }
    }
}

// ---------------- launch ----------------
extern "C" void kernel_launch(void* const* d_in, const int* in_sizes, int n_in,
                              void* d_out, int out_size) {
    const float* x      = (const float*)d_in[0];   // [N,D,M,M]
    const float* coeffs = (const float*)d_in[1];   // [D,S,5]
    const float* bias   = (const float*)d_in[2];   // [1,S,1,1]
    float* out = (float*)d_out;                    // [N,S,M,M]

    prep_coeffs_kernel<<<64, 256>>>(coeffs);
    stats_kernel<<<N_ * D_, 128>>>(x);
    pq_kernel<<<dim3(S_ / 8, N_), 128>>>(bias);
    gemm_tf32_kernel<<<dim3(32, N_), 256>>>(x, out);
}

// round 6
// speedup vs baseline: 1.3853x; 1.3853x over previous
#include <cuda_runtime.h>
#include <cstdint>

// Problem constants
#define N_ 32
#define D_ 128
#define S_ 128
#define M_ 64
#define MM_ (M_*M_)

// ---------------- scratch (__device__ globals; no allocations allowed) ----------------
__device__ float g_mcdg[N_*D_*M_*2]; // interleaved (mc, dg) pairs
__device__ float g_md[N_*D_];        // mean of diag
__device__ float g_ma[N_*D_];        // mean of all
__device__ float g_c2[D_*S_];        // coeffs[:,:,1], tf32-rounded, layout [d][s]
__device__ float g_c13[D_*S_*2];     // (0.5*c1, 0.5*c3) interleaved, layout [d][s][2]
__device__ float g_c45[D_*S_*2];     // (c4, c5) interleaved
__device__ float g_P[N_*S_*M_];      // P[n,s,v]
__device__ float g_Q[N_*S_];         // Q[n,s] (includes bias)

__device__ __forceinline__ float tf32r(float x) {
    uint32_t r;
    asm("cvt.rna.tf32.f32 %0, %1;" : "=r"(r) : "f"(x));
    return __uint_as_float(r);
}

__device__ __forceinline__ void cp16(void* s, const void* g) {
    uint32_t sa = (uint32_t)__cvta_generic_to_shared(s);
    asm volatile("cp.async.cg.shared.global [%0], [%1], 16;\n" :: "r"(sa), "l"(g));
}
#define CP_COMMIT() asm volatile("cp.async.commit_group;\n" ::: "memory")
#define CP_WAIT(Nn) asm volatile("cp.async.wait_group %0;\n" :: "n"(Nn) : "memory")

// ---------------- kernel 1: per-(n,d) stats  (+ coeff prep in extra blocks) ----------
__global__ __launch_bounds__(128) void stats_kernel(const float* __restrict__ x,
                                                    const float* __restrict__ coeffs) {
    if (blockIdx.x >= N_*D_) {
        // coeff-prep blocks: 64 blocks x 128 threads x 2 = 16384 = D*S
        int b = blockIdx.x - N_*D_;
        #pragma unroll
        for (int rep = 0; rep < 2; rep++) {
            int idx = (b * 2 + rep) * 128 + threadIdx.x;   // d*S + s
            const float* c = coeffs + idx * 5;
            g_c2[idx]        = tf32r(c[1]);
            g_c13[idx*2]     = 0.5f * c[0];
            g_c13[idx*2 + 1] = 0.5f * c[2];
            g_c45[idx*2]     = c[3];
            g_c45[idx*2 + 1] = c[4];
        }
        return;
    }

    int nd = blockIdx.x;
    const float* p = x + (size_t)nd * MM_;
    int t = threadIdx.x;
    int q = t & 15;
    int r = t >> 4;

    float4 acc = make_float4(0.f, 0.f, 0.f, 0.f);
    #pragma unroll
    for (int i = 0; i < 8; i++) {
        float4 v = *(const float4*)&p[(i*8 + r)*M_ + q*4];
        acc.x += v.x; acc.y += v.y; acc.z += v.z; acc.w += v.w;
    }

    __shared__ float4 part[128];
    __shared__ float  red[16], red2[16];
    __shared__ float  diags[64];
    part[t] = acc;
    if (t < M_) diags[t] = p[t*M_ + t];
    __syncthreads();

    if (t < 16) {
        float4 cs = part[t];
        #pragma unroll
        for (int rr = 1; rr < 8; rr++) {
            float4 v = part[rr*16 + t];
            cs.x += v.x; cs.y += v.y; cs.z += v.z; cs.w += v.w;
        }
        float mc[4] = { cs.x * (1.0f/M_), cs.y * (1.0f/M_),
                        cs.z * (1.0f/M_), cs.w * (1.0f/M_) };
        float2* out2 = ((float2*)g_mcdg) + nd*M_ + t*4;
        #pragma unroll
        for (int c = 0; c < 4; c++) {
            float2 md2; md2.x = mc[c]; md2.y = diags[t*4 + c];
            out2[c] = md2;
        }
        red[t]  = cs.x + cs.y + cs.z + cs.w;
        red2[t] = diags[t] + diags[t+16] + diags[t+32] + diags[t+48];
    }
    __syncthreads();
    if (t == 0) {
        float sa = 0.f, sd = 0.f;
        #pragma unroll
        for (int k = 0; k < 16; k++) { sa += red[k]; sd += red2[k]; }
        g_ma[nd] = sa * (1.0f/MM_);
        g_md[nd] = sd * (1.0f/M_);
    }
}

// ---------------- kernel 2: P[n,s,v] and Q[n,s] ----------------
// grid (S/8, N); 128 threads: v = tid&63, h = tid>>6 splits the d-loop.
// Q computed by the 64 h==1 threads with split-d (8 groups of 16) + smem reduce.
__global__ __launch_bounds__(128) void pq_kernel(const float* __restrict__ bias) {
    int n   = blockIdx.y;
    int s0  = blockIdx.x * 8;
    int tid = threadIdx.x;
    int v   = tid & 63;
    int h   = tid >> 6;

    __shared__ float2 c13s[D_][8];
    __shared__ float  psum[64][8];
    __shared__ float  qred[8][8];
    const float2* c13g = (const float2*)g_c13;
    for (int idx = tid; idx < D_ * 8; idx += 128) {
        int d = idx >> 3, t = idx & 7;
        c13s[d][t] = c13g[d*S_ + s0 + t];
    }
    __syncthreads();

    const float2* mcdg = (const float2*)g_mcdg;
    float acc[8] = {0.f,0.f,0.f,0.f,0.f,0.f,0.f,0.f};
    int base = (n*D_ + h*64)*M_ + v;
    #pragma unroll 8
    for (int dd = 0; dd < 64; dd++) {
        float2 m = mcdg[base + dd*M_];
        int d = h*64 + dd;
        #pragma unroll
        for (int t = 0; t < 8; t++) {
            float2 c = c13s[d][t];
            acc[t] += c.x * m.x + c.y * m.y;
        }
    }
    if (h == 1) {
        #pragma unroll
        for (int t = 0; t < 8; t++) psum[v][t] = acc[t];
    }
    __syncthreads();
    if (h == 0) {
        #pragma unroll
        for (int t = 0; t < 8; t++)
            g_P[(n*S_ + s0 + t)*M_ + v] = acc[t] + psum[v][t];
    } else {
        // Q: 64 threads -> 8 s x 8 d-groups of 16
        int sq  = v >> 3;          // 0..7
        int grp = v & 7;           // 0..7
        const float2* c45g = (const float2*)g_c45;
        float qacc = 0.f;
        int d0 = grp * 16;
        #pragma unroll
        for (int dd = 0; dd < 16; dd++) {
            int d = d0 + dd;
            float2 c = c45g[d*S_ + s0 + sq];
            qacc += c.x * g_md[n*D_ + d] + c.y * g_ma[n*D_ + d];
        }
        qred[sq][grp] = qacc;
    }
    __syncthreads();
    if (tid < 8) {
        float qv = 0.f;
        #pragma unroll
        for (int k = 0; k < 8; k++) qv += qred[tid][k];
        g_Q[n*S_ + s0 + tid] = qv + bias[s0 + tid];
    }
}

// ---------------- kernel 3: TF32 tensor-core GEMM ----------------
// A fragments via LDG (L1/L2-resident 64KB c2), B via 5-stage cp.async BK=16.
// CTA tile 128s x 128ij; 8 warps, warp (wr,wc): 32s x 64ij = 2m x 8n of m16n8k8.
// One barrier per k16 chunk (8 total), 64 mmas/warp between barriers.
#define BKP    16
#define STAGES 5
#define LDAS   136   // 128 + 8 skew -> conflict-free fragment gathers
#define NCHUNK (D_ / BKP)   // 8

__global__ __launch_bounds__(256, 2) void gemm_tf32_kernel(const float* __restrict__ x,
                                                           float* __restrict__ out) {
    __shared__ float Bs[STAGES][BKP][LDAS];   // B[k,ij] chunks only (43.5 KB)

    int n   = blockIdx.y;
    int bx  = blockIdx.x;          // ij chunk (128 wide)
    int tid = threadIdx.x;
    int w    = tid >> 5, lane = tid & 31;
    int g    = lane >> 2, tig = lane & 3;
    int wr   = w & 3;              // s0  = wr*32
    int wc   = w >> 2;             // ij0 = wc*64

    const float* xb = x + (size_t)(n * D_) * MM_ + bx * 128;

    // B loader: chunk = 16 rows x 128 cols = 512 float4 -> 2 per thread
    int lr = tid >> 5;             // rows lr and lr+8
    int lc = (tid & 31) * 4;
    const float* bgp = &xb[(size_t)lr * MM_ + lc];

    #pragma unroll
    for (int st = 0; st < STAGES - 1; st++) {
        cp16(&Bs[st][lr    ][lc], bgp + (size_t)(st*BKP    ) * MM_);
        cp16(&Bs[st][lr + 8][lc], bgp + (size_t)(st*BKP + 8) * MM_);
        CP_COMMIT();
    }

    float acc[2][8][4];
    #pragma unroll
    for (int mt = 0; mt < 2; mt++)
        #pragma unroll
        for (int nt = 0; nt < 8; nt++)
            #pragma unroll
            for (int v = 0; v < 4; v++) acc[mt][nt][v] = 0.f;

    int sb0 = wr * 32 + g;         // A s-index base (per thread)
    int sc = 0;                    // consume stage
    int sp = STAGES - 1;           // produce stage
    #pragma unroll 1
    for (int kt = 0; kt < NCHUNK; kt++) {
        // A fragments for this chunk: 16 LDG.32 from L1/L2-resident c2 (no smem, no wait)
        uint32_t a[2][2][4];       // [k8 blk][mt][frag]
        {
            int d0 = kt * BKP + tig;
            #pragma unroll
            for (int blk = 0; blk < 2; blk++) {
                const float* r0 = &g_c2[(d0 + blk*8    ) * S_ + sb0];
                const float* r4 = &g_c2[(d0 + blk*8 + 4) * S_ + sb0];
                #pragma unroll
                for (int mt = 0; mt < 2; mt++) {
                    a[blk][mt][0] = __float_as_uint(__ldg(r0 + mt*16));
                    a[blk][mt][1] = __float_as_uint(__ldg(r0 + mt*16 + 8));
                    a[blk][mt][2] = __float_as_uint(__ldg(r4 + mt*16));
                    a[blk][mt][3] = __float_as_uint(__ldg(r4 + mt*16 + 8));
                }
            }
        }

        CP_WAIT(3);                // chunk kt resident
        __syncthreads();           // stage sp fully consumed by all warps

        if (kt + STAGES - 1 < NCHUNK) {
            int d0 = (kt + STAGES - 1) * BKP;
            cp16(&Bs[sp][lr    ][lc], bgp + (size_t)(d0    ) * MM_);
            cp16(&Bs[sp][lr + 8][lc], bgp + (size_t)(d0 + 8) * MM_);
        }
        CP_COMMIT();               // empty groups at tail keep count uniform

        #pragma unroll
        for (int blk = 0; blk < 2; blk++) {
            int k0 = blk * 8;
            uint32_t b[8][2];
            #pragma unroll
            for (int nt = 0; nt < 8; nt++) {
                int cb = wc * 64 + nt * 8 + g;
                b[nt][0] = __float_as_uint(Bs[sc][k0 + tig    ][cb]);
                b[nt][1] = __float_as_uint(Bs[sc][k0 + tig + 4][cb]);
            }
            #pragma unroll
            for (int mt = 0; mt < 2; mt++)
                #pragma unroll
                for (int nt = 0; nt < 8; nt++) {
                    asm volatile(
                        "mma.sync.aligned.m16n8k8.row.col.f32.tf32.tf32.f32 "
                        "{%0,%1,%2,%3}, {%4,%5,%6,%7}, {%8,%9}, {%0,%1,%2,%3};"
                        : "+f"(acc[mt][nt][0]), "+f"(acc[mt][nt][1]),
                          "+f"(acc[mt][nt][2]), "+f"(acc[mt][nt][3])
                        : "r"(a[blk][mt][0]), "r"(a[blk][mt][1]),
                          "r"(a[blk][mt][2]), "r"(a[blk][mt][3]),
                          "r"(b[nt][0]), "r"(b[nt][1]));
                }
        }

        sc = (sc == STAGES-1) ? 0 : sc + 1;
        sp = (sp == STAGES-1) ? 0 : sp + 1;
    }

    // epilogue: out = acc + P[n,s,i] + P[n,s,j] + Q[n,s];  i = bx*2 + wc
    int i_row = bx * 2 + wc;
    #pragma unroll
    for (int mt = 0; mt < 2; mt++) {
        #pragma unroll
        for (int half = 0; half < 2; half++) {
            int s = wr * 32 + mt * 16 + g + half * 8;
            const float* Pn = &g_P[(n*S_ + s) * M_];
            float bias_si = Pn[i_row] + g_Q[n*S_ + s];
            size_t obase = (size_t)(n*S_ + s) * MM_ + (size_t)bx * 128 + wc * 64;
            #pragma unroll
            for (int nt = 0; nt < 8; nt++) {
                int j = nt * 8 + 2 * tig;
                float2 r;
                r.x = acc[mt][nt][half*2 + 0] + bias_si + Pn[j];
                r.y = acc[mt][nt][half*2 + 1] + bias_si + Pn[j + 1];
                *(float2*)&out[obase + j] = r;
            }
        }
    }
}

// ---------------- launch ----------------
extern "C" void kernel_launch(void* const* d_in, const int* in_sizes, int n_in,
                              void* d_out, int out_size) {
    const float* x      = (const float*)d_in[0];   // [N,D,M,M]
    const float* coeffs = (const float*)d_in[1];   // [D,S,5]
    const float* bias   = (const float*)d_in[2];   // [1,S,1,1]
    float* out = (float*)d_out;                    // [N,S,M,M]

    stats_kernel<<<N_ * D_ + 64, 128>>>(x, coeffs);   // stats + coeff prep
    pq_kernel<<<dim3(S_ / 8, N_), 128>>>(bias);
    gemm_tf32_kernel<<<dim3(32, N_), 256>>>(x, out);
}

// round 8
// speedup vs baseline: 1.5416x; 1.1128x over previous
#include <cuda_runtime.h>
#include <cstdint>

// Problem constants
#define N_ 32
#define D_ 128
#define S_ 128
#define M_ 64
#define MM_ (M_*M_)

// ---------------- scratch (__device__ globals; no allocations allowed) ----------------
__device__ float g_mcdg[N_*D_*M_*2]; // interleaved (mc, dg) pairs
__device__ float g_md[N_*D_];        // mean of diag
__device__ float g_ma[N_*D_];        // mean of all
__device__ float g_c2[D_*S_];        // coeffs[:,:,1], tf32-rounded, layout [d][s]
__device__ float g_c13[D_*S_*2];     // (0.5*c1, 0.5*c3) interleaved, layout [d][s][2]
__device__ float g_c45[D_*S_*2];     // (c4, c5) interleaved
__device__ float g_P[N_*S_*M_];      // P[n,s,v]
__device__ float g_Q[N_*S_];         // Q[n,s] (includes bias)

__device__ __forceinline__ float tf32r(float x) {
    uint32_t r;
    asm("cvt.rna.tf32.f32 %0, %1;" : "=r"(r) : "f"(x));
    return __uint_as_float(r);
}

__device__ __forceinline__ void cp16(void* s, const void* g) {
    uint32_t sa = (uint32_t)__cvta_generic_to_shared(s);
    asm volatile("cp.async.cg.shared.global [%0], [%1], 16;\n" :: "r"(sa), "l"(g));
}
#define CP_COMMIT() asm volatile("cp.async.commit_group;\n" ::: "memory")
#define CP_WAIT(Nn) asm volatile("cp.async.wait_group %0;\n" :: "n"(Nn) : "memory")

// ---------------- kernel 1: per-(n,d) stats  (+ coeff prep in extra blocks) ----------
__global__ __launch_bounds__(128) void stats_kernel(const float* __restrict__ x,
                                                    const float* __restrict__ coeffs) {
    if (blockIdx.x >= N_*D_) {
        int b = blockIdx.x - N_*D_;
        #pragma unroll
        for (int rep = 0; rep < 2; rep++) {
            int idx = (b * 2 + rep) * 128 + threadIdx.x;   // d*S + s
            const float* c = coeffs + idx * 5;
            g_c2[idx]        = tf32r(c[1]);
            g_c13[idx*2]     = 0.5f * c[0];
            g_c13[idx*2 + 1] = 0.5f * c[2];
            g_c45[idx*2]     = c[3];
            g_c45[idx*2 + 1] = c[4];
        }
        return;
    }

    int nd = blockIdx.x;
    const float* p = x + (size_t)nd * MM_;
    int t = threadIdx.x;
    int q = t & 15;
    int r = t >> 4;

    float4 acc = make_float4(0.f, 0.f, 0.f, 0.f);
    #pragma unroll
    for (int i = 0; i < 8; i++) {
        float4 v = *(const float4*)&p[(i*8 + r)*M_ + q*4];
        acc.x += v.x; acc.y += v.y; acc.z += v.z; acc.w += v.w;
    }

    __shared__ float4 part[128];
    __shared__ float  red[16], red2[16];
    __shared__ float  diags[64];
    part[t] = acc;
    if (t < M_) diags[t] = p[t*M_ + t];
    __syncthreads();

    if (t < 16) {
        float4 cs = part[t];
        #pragma unroll
        for (int rr = 1; rr < 8; rr++) {
            float4 v = part[rr*16 + t];
            cs.x += v.x; cs.y += v.y; cs.z += v.z; cs.w += v.w;
        }
        float mc[4] = { cs.x * (1.0f/M_), cs.y * (1.0f/M_),
                        cs.z * (1.0f/M_), cs.w * (1.0f/M_) };
        float2* out2 = ((float2*)g_mcdg) + nd*M_ + t*4;
        #pragma unroll
        for (int c = 0; c < 4; c++) {
            float2 md2; md2.x = mc[c]; md2.y = diags[t*4 + c];
            out2[c] = md2;
        }
        red[t]  = cs.x + cs.y + cs.z + cs.w;
        red2[t] = diags[t] + diags[t+16] + diags[t+32] + diags[t+48];
    }
    __syncthreads();
    if (t == 0) {
        float sa = 0.f, sd = 0.f;
        #pragma unroll
        for (int k = 0; k < 16; k++) { sa += red[k]; sd += red2[k]; }
        g_ma[nd] = sa * (1.0f/MM_);
        g_md[nd] = sd * (1.0f/M_);
    }
}

// ---------------- kernel 2: P[n,s,v] and Q[n,s] ----------------
__global__ __launch_bounds__(128) void pq_kernel(const float* __restrict__ bias) {
    int n   = blockIdx.y;
    int s0  = blockIdx.x * 8;
    int tid = threadIdx.x;
    int v   = tid & 63;
    int h   = tid >> 6;

    __shared__ float2 c13s[D_][8];
    __shared__ float  psum[64][8];
    __shared__ float  qred[8][8];
    const float2* c13g = (const float2*)g_c13;
    for (int idx = tid; idx < D_ * 8; idx += 128) {
        int d = idx >> 3, t = idx & 7;
        c13s[d][t] = c13g[d*S_ + s0 + t];
    }
    __syncthreads();

    const float2* mcdg = (const float2*)g_mcdg;
    float acc[8] = {0.f,0.f,0.f,0.f,0.f,0.f,0.f,0.f};
    int base = (n*D_ + h*64)*M_ + v;
    #pragma unroll 8
    for (int dd = 0; dd < 64; dd++) {
        float2 m = mcdg[base + dd*M_];
        int d = h*64 + dd;
        #pragma unroll
        for (int t = 0; t < 8; t++) {
            float2 c = c13s[d][t];
            acc[t] += c.x * m.x + c.y * m.y;
        }
    }
    if (h == 1) {
        #pragma unroll
        for (int t = 0; t < 8; t++) psum[v][t] = acc[t];
    }
    __syncthreads();
    if (h == 0) {
        #pragma unroll
        for (int t = 0; t < 8; t++)
            g_P[(n*S_ + s0 + t)*M_ + v] = acc[t] + psum[v][t];
    } else {
        int sq  = v >> 3;
        int grp = v & 7;
        const float2* c45g = (const float2*)g_c45;
        float qacc = 0.f;
        int d0 = grp * 16;
        #pragma unroll
        for (int dd = 0; dd < 16; dd++) {
            int d = d0 + dd;
            float2 c = c45g[d*S_ + s0 + sq];
            qacc += c.x * g_md[n*D_ + d] + c.y * g_ma[n*D_ + d];
        }
        qred[sq][grp] = qacc;
    }
    __syncthreads();
    if (tid < 8) {
        float qv = 0.f;
        #pragma unroll
        for (int k = 0; k < 8; k++) qv += qred[tid][k];
        g_Q[n*S_ + s0 + tid] = qv + bias[s0 + tid];
    }
}

// ---------------- kernel 3: TF32 tensor-core GEMM, BK=32 superchunks --------------
// A and B both via 3-stage cp.async (uniform depth), BK=32 -> 4 chunks total,
// ONE __syncthreads per chunk (4 barriers), 64 mmas + 96 conflict-free LDS per
// warp between barriers. Dynamic smem 104.4KB, 2 CTAs/SM.
#define BKP    32
#define STAGES 3
#define LDAS   136            // 128 + 8 skew -> conflict-free fragment gathers
#define NCHUNK (D_ / BKP)     // 4
#define ACHUNK_F (BKP * LDAS) // floats per A stage
#define SMEM_FLOATS (2 * STAGES * ACHUNK_F)

__global__ __launch_bounds__(256, 2) void gemm_tf32_kernel(const float* __restrict__ x,
                                                           float* __restrict__ out) {
    extern __shared__ float smem[];
    float (*As)[BKP][LDAS] = (float (*)[BKP][LDAS])smem;                       // [STAGES]
    float (*Bs)[BKP][LDAS] = (float (*)[BKP][LDAS])(smem + STAGES * ACHUNK_F); // [STAGES]

    int n   = blockIdx.y;
    int bx  = blockIdx.x;          // ij chunk (128 wide)
    int tid = threadIdx.x;
    int w    = tid >> 5, lane = tid & 31;
    int g    = lane >> 2, tig = lane & 3;
    int wr   = w & 3;              // s0  = wr*32
    int wc   = w >> 2;             // ij0 = wc*64

    const float* xb = x + (size_t)(n * D_) * MM_ + bx * 128;

    // loader: each chunk (A or B) = 32 rows x 128 cols = 1024 float4 -> 4 per thread
    int lr = tid >> 5;             // base row; rows lr, lr+8, lr+16, lr+24
    int lc = (tid & 31) * 4;

    // prologue: prefetch chunks 0,1 (A+B per group)
    #pragma unroll
    for (int st = 0; st < STAGES - 1; st++) {
        int d0 = st * BKP;
        #pragma unroll
        for (int i = 0; i < 4; i++) {
            cp16(&As[st][lr + i*8][lc], &g_c2[(d0 + lr + i*8) * S_ + lc]);
            cp16(&Bs[st][lr + i*8][lc], &xb[(size_t)(d0 + lr + i*8) * MM_ + lc]);
        }
        CP_COMMIT();
    }

    float acc[2][8][4];
    #pragma unroll
    for (int mt = 0; mt < 2; mt++)
        #pragma unroll
        for (int nt = 0; nt < 8; nt++)
            #pragma unroll
            for (int v = 0; v < 4; v++) acc[mt][nt][v] = 0.f;

    int sc = 0;                    // consume stage
    int sp = STAGES - 1;           // produce stage
    #pragma unroll 1
    for (int kt = 0; kt < NCHUNK; kt++) {
        CP_WAIT(1);                // chunk kt resident
        __syncthreads();           // stage sp fully consumed by all warps

        if (kt + STAGES - 1 < NCHUNK) {
            int d0 = (kt + STAGES - 1) * BKP;
            #pragma unroll
            for (int i = 0; i < 4; i++) {
                cp16(&As[sp][lr + i*8][lc], &g_c2[(d0 + lr + i*8) * S_ + lc]);
                cp16(&Bs[sp][lr + i*8][lc], &xb[(size_t)(d0 + lr + i*8) * MM_ + lc]);
            }
        }
        CP_COMMIT();               // empty groups at tail keep count uniform

        // compute 4 k8-blocks on stage sc: 64 mmas/warp, no global latency inside
        #pragma unroll
        for (int blk = 0; blk < 4; blk++) {
            int k0 = blk * 8;
            uint32_t a[2][4], b[8][2];
            #pragma unroll
            for (int mt = 0; mt < 2; mt++) {
                int sb = wr * 32 + mt * 16;
                a[mt][0] = __float_as_uint(As[sc][k0 + tig    ][sb + g    ]);
                a[mt][1] = __float_as_uint(As[sc][k0 + tig    ][sb + g + 8]);
                a[mt][2] = __float_as_uint(As[sc][k0 + tig + 4][sb + g    ]);
                a[mt][3] = __float_as_uint(As[sc][k0 + tig + 4][sb + g + 8]);
            }
            #pragma unroll
            for (int nt = 0; nt < 8; nt++) {
                int cb = wc * 64 + nt * 8 + g;
                b[nt][0] = __float_as_uint(Bs[sc][k0 + tig    ][cb]);
                b[nt][1] = __float_as_uint(Bs[sc][k0 + tig + 4][cb]);
            }
            #pragma unroll
            for (int mt = 0; mt < 2; mt++)
                #pragma unroll
                for (int nt = 0; nt < 8; nt++) {
                    asm volatile(
                        "mma.sync.aligned.m16n8k8.row.col.f32.tf32.tf32.f32 "
                        "{%0,%1,%2,%3}, {%4,%5,%6,%7}, {%8,%9}, {%0,%1,%2,%3};"
                        : "+f"(acc[mt][nt][0]), "+f"(acc[mt][nt][1]),
                          "+f"(acc[mt][nt][2]), "+f"(acc[mt][nt][3])
                        : "r"(a[mt][0]), "r"(a[mt][1]), "r"(a[mt][2]), "r"(a[mt][3]),
                          "r"(b[nt][0]), "r"(b[nt][1]));
                }
        }

        sc = (sc == STAGES-1) ? 0 : sc + 1;
        sp = (sp == STAGES-1) ? 0 : sp + 1;
    }

    // epilogue: out = acc + P[n,s,i] + P[n,s,j] + Q[n,s];  i = bx*2 + wc
    int i_row = bx * 2 + wc;
    #pragma unroll
    for (int mt = 0; mt < 2; mt++) {
        #pragma unroll
        for (int half = 0; half < 2; half++) {
            int s = wr * 32 + mt * 16 + g + half * 8;
            const float* Pn = &g_P[(n*S_ + s) * M_];
            float bias_si = Pn[i_row] + g_Q[n*S_ + s];
            size_t obase = (size_t)(n*S_ + s) * MM_ + (size_t)bx * 128 + wc * 64;
            #pragma unroll
            for (int nt = 0; nt < 8; nt++) {
                int j = nt * 8 + 2 * tig;
                float2 r;
                r.x = acc[mt][nt][half*2 + 0] + bias_si + Pn[j];
                r.y = acc[mt][nt][half*2 + 1] + bias_si + Pn[j + 1];
                *(float2*)&out[obase + j] = r;
            }
        }
    }
}

// ---------------- launch ----------------
extern "C" void kernel_launch(void* const* d_in, const int* in_sizes, int n_in,
                              void* d_out, int out_size) {
    const float* x      = (const float*)d_in[0];   // [N,D,M,M]
    const float* coeffs = (const float*)d_in[1];   // [D,S,5]
    const float* bias   = (const float*)d_in[2];   // [1,S,1,1]
    float* out = (float*)d_out;                    // [N,S,M,M]

    static int smem_set = 0;
    if (!smem_set) {
        cudaFuncSetAttribute(gemm_tf32_kernel,
                             cudaFuncAttributeMaxDynamicSharedMemorySize,
                             SMEM_FLOATS * sizeof(float));
        smem_set = 1;
    }

    stats_kernel<<<N_ * D_ + 64, 128>>>(x, coeffs);   // stats + coeff prep
    pq_kernel<<<dim3(S_ / 8, N_), 128>>>(bias);
    gemm_tf32_kernel<<<dim3(32, N_), 256, SMEM_FLOATS * sizeof(float)>>>(x, out);
}